// round 5
// baseline (speedup 1.0000x reference)
#include <cuda_runtime.h>
#include <cuda_fp16.h>
#include <cstdint>

#define BB 8
#define SQL 2048
#define SKL 2048
#define DDIM 1024

// ---------------- static device scratch (no allocation allowed) ----------------
__device__ __align__(256) __half g_qh [BB * SQL * DDIM];
__device__ __align__(256) __half g_ql [BB * SQL * DDIM];
__device__ __align__(256) __half g_kh [BB * SKL * DDIM];
__device__ __align__(256) __half g_kl [BB * SKL * DDIM];
__device__ __align__(256) __half g_vh [BB * SKL * DDIM];
__device__ __align__(256) __half g_vl [BB * SKL * DDIM];
__device__ __align__(256) __half g_Wqh[DDIM * DDIM];
__device__ __align__(256) __half g_Wql[DDIM * DDIM];
__device__ __align__(256) __half g_Wkh[DDIM * DDIM];
__device__ __align__(256) __half g_Wkl[DDIM * DDIM];
__device__ __align__(256) __half g_Wvh[DDIM * DDIM];
__device__ __align__(256) __half g_Wvl[DDIM * DDIM];
__device__ __align__(256) __half g_Qph[BB * SQL * DDIM];
__device__ __align__(256) __half g_Qpl[BB * SQL * DDIM];
__device__ __align__(256) __half g_Kph[BB * SKL * DDIM];
__device__ __align__(256) __half g_Kpl[BB * SKL * DDIM];
__device__ __align__(256) __half g_VpT[DDIM * BB * SKL];   // [dv][b*SK + sk]
__device__ __align__(256) float  g_S  [(size_t)BB * SQL * SKL];
__device__ __align__(256) __half g_P  [(size_t)BB * SQL * SKL];

__device__ __forceinline__ uint32_t smem_u32(const void* p) {
    return (uint32_t)__cvta_generic_to_shared(p);
}

// ---------------- fp32 -> (hi,lo) fp16 split convert ----------------
__global__ void cvt_split(const float* __restrict__ x, __half* __restrict__ hi,
                          __half* __restrict__ lo, int n4) {
    int i = blockIdx.x * blockDim.x + threadIdx.x;
    if (i < n4) {
        float4 v = ((const float4*)x)[i];
        __half h0 = __float2half_rn(v.x), h1 = __float2half_rn(v.y);
        __half h2 = __float2half_rn(v.z), h3 = __float2half_rn(v.w);
        __half l0 = __float2half_rn(v.x - __half2float(h0));
        __half l1 = __float2half_rn(v.y - __half2float(h1));
        __half l2 = __float2half_rn(v.z - __half2float(h2));
        __half l3 = __float2half_rn(v.w - __half2float(h3));
        ((__half2*)hi)[2 * i + 0] = __halves2half2(h0, h1);
        ((__half2*)hi)[2 * i + 1] = __halves2half2(h2, h3);
        ((__half2*)lo)[2 * i + 0] = __halves2half2(l0, l1);
        ((__half2*)lo)[2 * i + 1] = __halves2half2(l2, l3);
    }
}

// ---------------- weight transpose + split: W[k][n] f32 -> WT{h,l}[n][k] ----------------
__global__ void wtrans_split(const float* __restrict__ W, __half* __restrict__ WTh,
                             __half* __restrict__ WTl) {
    __shared__ float tile[32][33];
    int kb = blockIdx.x * 32, nb = blockIdx.y * 32;
    int tx = threadIdx.x, ty = threadIdx.y;
#pragma unroll
    for (int r = 0; r < 4; r++)
        tile[ty + 8 * r][tx] = W[(size_t)(kb + ty + 8 * r) * DDIM + nb + tx];
    __syncthreads();
#pragma unroll
    for (int r = 0; r < 4; r++) {
        float x = tile[tx][ty + 8 * r];
        __half h = __float2half_rn(x);
        size_t o = (size_t)(nb + ty + 8 * r) * DDIM + kb + tx;
        WTh[o] = h;
        WTl[o] = __float2half_rn(x - __half2float(h));
    }
}

#define LDS 40     // padded k-stride in halves (32 + 8) -> conflict-free ldmatrix
#define OPH 5120   // halves per operand tile (128 * 40)

template <int N> __device__ __forceinline__ void cpwait() {
    asm volatile("cp.async.wait_group %0;\n" ::"n"(N));
}

// =====================================================================
// fp16 tensor-core GEMM: C[128m x 128n] tile = A[M,K] * Bt[N,K]^T.
// SPLIT: 3 mma passes (Ah*Bh + Ah*Bl + Al*Bh), fp32 accum.
// Deep cp.async pipeline (NSTG stages of k=32), ONE barrier per k-iter,
// register double-buffered ldmatrix over the two k16 slices.
// MODE 0: c += bias, split-store hi/lo fp16
// MODE 1: tanh(c + bias), TRANSPOSED fp16 store (ldc = row len of C^T)
// MODE 2: fp32 store (+ batch offset sC)
// =====================================================================
template <int MODE, bool SPLIT>
__global__ void __launch_bounds__(256, 1)
gemm_tc(const __half* __restrict__ Ah_, const __half* __restrict__ Al_,
        const __half* __restrict__ Bh_, const __half* __restrict__ Bl_,
        void* __restrict__ C0b, void* __restrict__ C1b,
        const float* __restrict__ bias,
        int K, int lda, int ldb, int ldc,
        long sA, long sB, long sC) {
    constexpr int NSTG = SPLIT ? 4 : 6;
    constexpr int NAR  = SPLIT ? 4 : 2;
    constexpr int STGH = NAR * OPH;   // halves per stage

    extern __shared__ __align__(1024) __half smem[];

    const __half* Ah = Ah_ + (size_t)blockIdx.z * sA;
    const __half* Al = SPLIT ? (Al_ + (size_t)blockIdx.z * sA) : nullptr;
    const __half* Bh = Bh_ + (size_t)blockIdx.z * sB;
    const __half* Bl = SPLIT ? (Bl_ + (size_t)blockIdx.z * sB) : nullptr;

    const int tid  = threadIdx.x;
    const int lane = tid & 31;
    const int warp = tid >> 5;
    const int wm = warp & 1;     // 2 warp-rows of 64
    const int wn = warp >> 1;    // 4 warp-cols of 32
    const int gm = blockIdx.y * 128;
    const int gn = blockIdx.x * 128;
    const int nk = K >> 5;

    float c[4][4][4];
#pragma unroll
    for (int i = 0; i < 4; i++)
#pragma unroll
        for (int j = 0; j < 4; j++)
#pragma unroll
            for (int r = 0; r < 4; r++) c[i][j][r] = 0.f;

    auto load_stage = [&](int s, int kt) {
        if (kt < nk) {
            __half* stg = smem + s * STGH;
            const int k0 = kt * 32;
#pragma unroll
            for (int op = 0; op < NAR; op++) {
                const __half* base;
                int r0, ld;
                if (SPLIT) {
                    base = (op == 0) ? Ah : (op == 1) ? Al : (op == 2) ? Bh : Bl;
                    r0 = (op < 2) ? gm : gn;
                    ld = (op < 2) ? lda : ldb;
                } else {
                    base = (op == 0) ? Ah : Bh;
                    r0 = (op == 0) ? gm : gn;
                    ld = (op == 0) ? lda : ldb;
                }
                __half* dst0 = stg + op * OPH;
#pragma unroll
                for (int it = 0; it < 2; it++) {
                    int qq = tid + it * 256;
                    int r = qq >> 2, cc = qq & 3;
                    uint32_t dst = smem_u32(dst0 + r * LDS + cc * 8);
                    const __half* src = base + (size_t)(r0 + r) * ld + k0 + cc * 8;
                    asm volatile("cp.async.cg.shared.global [%0], [%1], 16;\n"
                                 ::"r"(dst), "l"(src));
                }
            }
        }
        asm volatile("cp.async.commit_group;\n");
    };

    // prologue: stages 0..NSTG-2
#pragma unroll
    for (int t = 0; t < NSTG - 1; t++) load_stage(t, t);

    uint32_t ah[2][4][4], al[2][4][4], bh[2][4][2], bl[2][4][2];

    auto load_frags = [&](int buf, const __half* stg, int ks) {
        const __half* sah = stg;
        const __half* sbh = stg + (SPLIT ? 2 : 1) * OPH;
#pragma unroll
        for (int i = 0; i < 4; i++) {
            int ro = (wm * 64 + i * 16 + (lane & 15)) * LDS + ks * 16 + (lane >> 4) * 8;
            uint32_t a0 = smem_u32(sah + ro);
            asm volatile("ldmatrix.sync.aligned.m8n8.x4.shared.b16 {%0,%1,%2,%3}, [%4];"
                         : "=r"(ah[buf][i][0]), "=r"(ah[buf][i][1]),
                           "=r"(ah[buf][i][2]), "=r"(ah[buf][i][3])
                         : "r"(a0));
            if (SPLIT) {
                uint32_t a1 = smem_u32(sah + OPH + ro);
                asm volatile("ldmatrix.sync.aligned.m8n8.x4.shared.b16 {%0,%1,%2,%3}, [%4];"
                             : "=r"(al[buf][i][0]), "=r"(al[buf][i][1]),
                               "=r"(al[buf][i][2]), "=r"(al[buf][i][3])
                             : "r"(a1));
            }
        }
#pragma unroll
        for (int j = 0; j < 4; j++) {
            int ro = (wn * 32 + j * 8 + (lane & 7)) * LDS + ks * 16 + ((lane >> 3) & 1) * 8;
            uint32_t b0 = smem_u32(sbh + ro);
            asm volatile("ldmatrix.sync.aligned.m8n8.x2.shared.b16 {%0,%1}, [%2];"
                         : "=r"(bh[buf][j][0]), "=r"(bh[buf][j][1]) : "r"(b0));
            if (SPLIT) {
                uint32_t b1 = smem_u32(sbh + OPH + ro);
                asm volatile("ldmatrix.sync.aligned.m8n8.x2.shared.b16 {%0,%1}, [%2];"
                             : "=r"(bl[buf][j][0]), "=r"(bl[buf][j][1]) : "r"(b1));
            }
        }
    };

#define MMA16(AA, BB_)                                                                       \
    asm volatile("mma.sync.aligned.m16n8k16.row.col.f32.f16.f16.f32 "                        \
                 "{%0,%1,%2,%3}, {%4,%5,%6,%7}, {%8,%9}, {%0,%1,%2,%3};"                     \
                 : "+f"(c[i][j][0]), "+f"(c[i][j][1]), "+f"(c[i][j][2]), "+f"(c[i][j][3])    \
                 : "r"(AA[i][0]), "r"(AA[i][1]), "r"(AA[i][2]), "r"(AA[i][3]),               \
                   "r"(BB_[j][0]), "r"(BB_[j][1]))

    auto domma = [&](int buf) {
#pragma unroll
        for (int i = 0; i < 4; i++)
#pragma unroll
            for (int j = 0; j < 4; j++) MMA16(ah[buf], bh[buf]);
        if (SPLIT) {
#pragma unroll
            for (int i = 0; i < 4; i++)
#pragma unroll
                for (int j = 0; j < 4; j++) MMA16(ah[buf], bl[buf]);
#pragma unroll
            for (int i = 0; i < 4; i++)
#pragma unroll
                for (int j = 0; j < 4; j++) MMA16(al[buf], bh[buf]);
        }
    };
#undef MMA16

    for (int kt = 0; kt < nk; kt++) {
        cpwait<NSTG - 2>();          // stage kt complete
        __syncthreads();             // slot (kt-1)%NSTG free for reuse

        const __half* stg = smem + (kt % NSTG) * STGH;
        load_frags(0, stg, 0);
        load_frags(1, stg, 1);
        load_stage((kt + NSTG - 1) % NSTG, kt + NSTG - 1);  // always commits
        domma(0);
        domma(1);
    }

    __syncthreads();

    if (MODE == 0) {
        __half* Chi = (__half*)C0b;
        __half* Clo = (__half*)C1b;
#pragma unroll
        for (int i = 0; i < 4; i++)
#pragma unroll
            for (int j = 0; j < 4; j++) {
                int row = gm + wm * 64 + i * 16 + (lane >> 2);
                int col = gn + wn * 32 + j * 8 + ((lane & 3) << 1);
                float b0 = bias[col], b1 = bias[col + 1];
#pragma unroll
                for (int h = 0; h < 2; h++) {
                    float v0 = c[i][j][2 * h + 0] + b0;
                    float v1 = c[i][j][2 * h + 1] + b1;
                    __half h0 = __float2half_rn(v0), h1 = __float2half_rn(v1);
                    __half l0 = __float2half_rn(v0 - __half2float(h0));
                    __half l1 = __float2half_rn(v1 - __half2float(h1));
                    size_t o = (size_t)(row + 8 * h) * ldc + col;
                    *(__half2*)(Chi + o) = __halves2half2(h0, h1);
                    *(__half2*)(Clo + o) = __halves2half2(l0, l1);
                }
            }
    } else if (MODE == 2) {
        float* C = (float*)C0b + (size_t)blockIdx.z * sC;
#pragma unroll
        for (int i = 0; i < 4; i++)
#pragma unroll
            for (int j = 0; j < 4; j++) {
                int row = gm + wm * 64 + i * 16 + (lane >> 2);
                int col = gn + wn * 32 + j * 8 + ((lane & 3) << 1);
                float2 v0; v0.x = c[i][j][0]; v0.y = c[i][j][1];
                float2 v1; v1.x = c[i][j][2]; v1.y = c[i][j][3];
                *(float2*)(C + (size_t)row * ldc + col) = v0;
                *(float2*)(C + (size_t)(row + 8) * ldc + col) = v1;
            }
    } else {  // MODE 1: tanh + transposed fp16 store via smem staging
        __half* st = smem;  // 128*136 halves = 34816 B, fits
#pragma unroll
        for (int i = 0; i < 4; i++)
#pragma unroll
            for (int j = 0; j < 4; j++) {
                int row = wm * 64 + i * 16 + (lane >> 2);
                int col = wn * 32 + j * 8 + ((lane & 3) << 1);
                float b0 = bias[gn + col], b1 = bias[gn + col + 1];
                st[(col + 0) * 136 + row + 0] = __float2half_rn(tanhf(c[i][j][0] + b0));
                st[(col + 1) * 136 + row + 0] = __float2half_rn(tanhf(c[i][j][1] + b1));
                st[(col + 0) * 136 + row + 8] = __float2half_rn(tanhf(c[i][j][2] + b0));
                st[(col + 1) * 136 + row + 8] = __float2half_rn(tanhf(c[i][j][3] + b1));
            }
        __syncthreads();
        __half* C = (__half*)C0b;
        for (int qq = tid; qq < 128 * 128 / 8; qq += 256) {
            int n = qq >> 4, m = (qq & 15) << 3;     // 8 halves per thread
            *(uint4*)(C + (size_t)(gn + n) * ldc + gm + m) = *(const uint4*)(st + n * 136 + m);
        }
    }
}

// ---------------- softmax over rows of S (+ int32 bool-mask add) -> fp16 P ----------------
__global__ void softmax_k(const float* __restrict__ S, const int* __restrict__ mask,
                          __half* __restrict__ P) {
    int row = blockIdx.x;
    int b = row >> 11;
    const float* s = S + (size_t)row * SKL;
    const int* mk = mask + (size_t)b * SKL;
    int t = threadIdx.x;

    float vals[8];
    float mx = -3.4e38f;
#pragma unroll
    for (int i = 0; i < 8; i++) {
        int j = t + i * 256;
        float v = s[j] + (mk[j] ? 1.0f : 0.0f);
        vals[i] = v;
        mx = fmaxf(mx, v);
    }
    __shared__ float red[8];
#pragma unroll
    for (int o = 16; o > 0; o >>= 1) mx = fmaxf(mx, __shfl_xor_sync(0xffffffffu, mx, o));
    if ((t & 31) == 0) red[t >> 5] = mx;
    __syncthreads();
    if (t == 0) {
        float v = red[0];
        for (int i = 1; i < 8; i++) v = fmaxf(v, red[i]);
        red[0] = v;
    }
    __syncthreads();
    mx = red[0];

    float sum = 0.f;
#pragma unroll
    for (int i = 0; i < 8; i++) {
        vals[i] = __expf(vals[i] - mx);
        sum += vals[i];
    }
#pragma unroll
    for (int o = 16; o > 0; o >>= 1) sum += __shfl_xor_sync(0xffffffffu, sum, o);
    __syncthreads();
    if ((t & 31) == 0) red[t >> 5] = sum;
    __syncthreads();
    if (t == 0) {
        float v = 0.f;
        for (int i = 0; i < 8; i++) v += red[i];
        red[0] = v;
    }
    __syncthreads();
    float inv = 1.0f / red[0];
#pragma unroll
    for (int i = 0; i < 8; i++) {
        int j = t + i * 256;
        P[(size_t)row * SKL + j] = __float2half_rn(vals[i] * inv);
    }
}

// ---------------- launch ----------------
extern "C" void kernel_launch(void* const* d_in, const int* in_sizes, int n_in,
                              void* d_out, int out_size) {
    const float* q  = (const float*)d_in[0];
    const float* k  = (const float*)d_in[1];
    const float* v  = (const float*)d_in[2];
    const int*   mask = (const int*)d_in[3];
    const float* Wq = (const float*)d_in[4];
    const float* bq = (const float*)d_in[5];
    const float* Wk = (const float*)d_in[6];
    const float* bk = (const float*)d_in[7];
    const float* Wv = (const float*)d_in[8];
    const float* bv = (const float*)d_in[9];

    __half *qh, *ql, *kh, *kl, *vh, *vl;
    __half *Wqh, *Wql, *Wkh, *Wkl, *Wvh, *Wvl;
    __half *Qph, *Qpl, *Kph, *Kpl, *VpT, *P;
    float* S;
    cudaGetSymbolAddress((void**)&qh,  g_qh);  cudaGetSymbolAddress((void**)&ql,  g_ql);
    cudaGetSymbolAddress((void**)&kh,  g_kh);  cudaGetSymbolAddress((void**)&kl,  g_kl);
    cudaGetSymbolAddress((void**)&vh,  g_vh);  cudaGetSymbolAddress((void**)&vl,  g_vl);
    cudaGetSymbolAddress((void**)&Wqh, g_Wqh); cudaGetSymbolAddress((void**)&Wql, g_Wql);
    cudaGetSymbolAddress((void**)&Wkh, g_Wkh); cudaGetSymbolAddress((void**)&Wkl, g_Wkl);
    cudaGetSymbolAddress((void**)&Wvh, g_Wvh); cudaGetSymbolAddress((void**)&Wvl, g_Wvl);
    cudaGetSymbolAddress((void**)&Qph, g_Qph); cudaGetSymbolAddress((void**)&Qpl, g_Qpl);
    cudaGetSymbolAddress((void**)&Kph, g_Kph); cudaGetSymbolAddress((void**)&Kpl, g_Kpl);
    cudaGetSymbolAddress((void**)&VpT, g_VpT);
    cudaGetSymbolAddress((void**)&S,   g_S);
    cudaGetSymbolAddress((void**)&P,   g_P);

    const int SM_SPLIT  = 4 * 4 * OPH * (int)sizeof(__half);  // 4 stages * 4 ops * 10240B = 163840
    const int SM_SINGLE = 6 * 2 * OPH * (int)sizeof(__half);  // 6 stages * 2 ops * 10240B = 122880
    cudaFuncSetAttribute(gemm_tc<0, true>,  cudaFuncAttributeMaxDynamicSharedMemorySize, SM_SPLIT);
    cudaFuncSetAttribute(gemm_tc<1, true>,  cudaFuncAttributeMaxDynamicSharedMemorySize, SM_SPLIT);
    cudaFuncSetAttribute(gemm_tc<2, true>,  cudaFuncAttributeMaxDynamicSharedMemorySize, SM_SPLIT);
    cudaFuncSetAttribute(gemm_tc<2, false>, cudaFuncAttributeMaxDynamicSharedMemorySize, SM_SINGLE);

    int n4 = BB * SQL * DDIM / 4;
    cvt_split<<<n4 / 256, 256>>>(q, qh, ql, n4);
    cvt_split<<<n4 / 256, 256>>>(k, kh, kl, n4);
    cvt_split<<<n4 / 256, 256>>>(v, vh, vl, n4);

    dim3 wtg(32, 32), wtb(32, 8);
    wtrans_split<<<wtg, wtb>>>(Wq, Wqh, Wql);
    wtrans_split<<<wtg, wtb>>>(Wk, Wkh, Wkl);
    wtrans_split<<<wtg, wtb>>>(Wv, Wvh, Wvl);

    // Projections: M = 16384, N = 1024, K = 1024 (3-pass split)
    gemm_tc<0, true><<<dim3(8, 128, 1), 256, SM_SPLIT>>>(
        qh, ql, Wqh, Wql, Qph, Qpl, bq, 1024, 1024, 1024, 1024, 0, 0, 0);
    gemm_tc<0, true><<<dim3(8, 128, 1), 256, SM_SPLIT>>>(
        kh, kl, Wkh, Wkl, Kph, Kpl, bk, 1024, 1024, 1024, 1024, 0, 0, 0);
    // V projection: tanh + transposed store into VpT[dv][b*SK+sk]
    gemm_tc<1, true><<<dim3(8, 128, 1), 256, SM_SPLIT>>>(
        vh, vl, Wvh, Wvl, VpT, nullptr, bv, 1024, 1024, 1024, BB * SKL, 0, 0, 0);

    // Scores: per batch, S = Qp Kp^T  (M=N=2048, K=1024), 3-pass split
    gemm_tc<2, true><<<dim3(16, 16, BB), 256, SM_SPLIT>>>(
        Qph, Qpl, Kph, Kpl, S, nullptr, nullptr, 1024, 1024, 1024, 2048,
        (long)SQL * DDIM, (long)SKL * DDIM, (long)SQL * SKL);

    // Softmax (+int mask) -> P fp16
    softmax_k<<<BB * SQL, 256>>>(S, mask, P);

    // Output: per batch, O = P · VpT^T  (M=2048, N=1024, K=2048), single-pass fp16
    gemm_tc<2, false><<<dim3(8, 16, BB), 256, SM_SINGLE>>>(
        P, nullptr, VpT, nullptr, d_out, nullptr, nullptr, 2048, 2048, BB * SKL, 1024,
        (long)SQL * SKL, (long)SKL, (long)SQL * DDIM);
}

// round 6
// speedup vs baseline: 1.7714x; 1.7714x over previous
#include <cuda_runtime.h>
#include <cuda_fp16.h>
#include <cstdint>

#define BB 8
#define SQL 2048
#define SKL 2048
#define DDIM 1024

// ---------------- static device scratch (no allocation allowed) ----------------
__device__ __align__(256) __half g_qh [BB * SQL * DDIM];
__device__ __align__(256) __half g_ql [BB * SQL * DDIM];
__device__ __align__(256) __half g_kh [BB * SKL * DDIM];
__device__ __align__(256) __half g_kl [BB * SKL * DDIM];
__device__ __align__(256) __half g_vh [BB * SKL * DDIM];
__device__ __align__(256) __half g_vl [BB * SKL * DDIM];
__device__ __align__(256) __half g_Wqh[DDIM * DDIM];
__device__ __align__(256) __half g_Wql[DDIM * DDIM];
__device__ __align__(256) __half g_Wkh[DDIM * DDIM];
__device__ __align__(256) __half g_Wkl[DDIM * DDIM];
__device__ __align__(256) __half g_Wvh[DDIM * DDIM];
__device__ __align__(256) __half g_Wvl[DDIM * DDIM];
__device__ __align__(256) __half g_Qph[BB * SQL * DDIM];
__device__ __align__(256) __half g_Qpl[BB * SQL * DDIM];
__device__ __align__(256) __half g_Kph[BB * SKL * DDIM];
__device__ __align__(256) __half g_Kpl[BB * SKL * DDIM];
__device__ __align__(256) __half g_VpT[DDIM * BB * SKL];   // [dv][b*SK + sk]
__device__ __align__(256) float  g_S  [(size_t)BB * SQL * SKL];
__device__ __align__(256) __half g_P  [(size_t)BB * SQL * SKL];

__device__ __forceinline__ uint32_t smem_u32(const void* p) {
    return (uint32_t)__cvta_generic_to_shared(p);
}

// ---------------- fp32 -> (hi,lo) fp16 split convert ----------------
__global__ void cvt_split(const float* __restrict__ x, __half* __restrict__ hi,
                          __half* __restrict__ lo, int n4) {
    int i = blockIdx.x * blockDim.x + threadIdx.x;
    if (i < n4) {
        float4 v = ((const float4*)x)[i];
        __half h0 = __float2half_rn(v.x), h1 = __float2half_rn(v.y);
        __half h2 = __float2half_rn(v.z), h3 = __float2half_rn(v.w);
        __half l0 = __float2half_rn(v.x - __half2float(h0));
        __half l1 = __float2half_rn(v.y - __half2float(h1));
        __half l2 = __float2half_rn(v.z - __half2float(h2));
        __half l3 = __float2half_rn(v.w - __half2float(h3));
        ((__half2*)hi)[2 * i + 0] = __halves2half2(h0, h1);
        ((__half2*)hi)[2 * i + 1] = __halves2half2(h2, h3);
        ((__half2*)lo)[2 * i + 0] = __halves2half2(l0, l1);
        ((__half2*)lo)[2 * i + 1] = __halves2half2(l2, l3);
    }
}

// ---------------- weight transpose + split: W[k][n] f32 -> WT{h,l}[n][k] ----------------
__global__ void wtrans_split(const float* __restrict__ W, __half* __restrict__ WTh,
                             __half* __restrict__ WTl) {
    __shared__ float tile[32][33];
    int kb = blockIdx.x * 32, nb = blockIdx.y * 32;
    int tx = threadIdx.x, ty = threadIdx.y;
#pragma unroll
    for (int r = 0; r < 4; r++)
        tile[ty + 8 * r][tx] = W[(size_t)(kb + ty + 8 * r) * DDIM + nb + tx];
    __syncthreads();
#pragma unroll
    for (int r = 0; r < 4; r++) {
        float x = tile[tx][ty + 8 * r];
        __half h = __float2half_rn(x);
        size_t o = (size_t)(nb + ty + 8 * r) * DDIM + kb + tx;
        WTh[o] = h;
        WTl[o] = __float2half_rn(x - __half2float(h));
    }
}

// XOR swizzle: 64-byte k-rows (32 halves), 4 chunks of 16B per row.
// chunk' = chunk ^ ((row>>1)&3) -> 8-row ldmatrix hits 8 distinct 16B bank slots.
#define OPB 8192   // bytes per operand tile: 128 rows * 64 B

__device__ __forceinline__ uint32_t swz_off(int row, int chunk) {
    return (uint32_t)(row * 64 + ((chunk ^ ((row >> 1) & 3)) << 4));
}

template <int N> __device__ __forceinline__ void cpwait() {
    asm volatile("cp.async.wait_group %0;\n" ::"n"(N));
}

// =====================================================================
// fp16 tensor-core GEMM: C[128m x 128n] tile = A[M,K] * Bt[N,K]^T.
// SPLIT: 3 mma passes (Ah*Bh + Ah*Bl + Al*Bh), fp32 accum.
// NSTG-stage cp.async pipeline over k=32 chunks, ONE barrier per k-iter,
// XOR-swizzled unpadded smem, forced 2 CTAs/SM.
// MODE 0: c += bias, split-store hi/lo fp16
// MODE 1: tanh(c + bias), TRANSPOSED fp16 store (ldc = row len of C^T)
// MODE 2: fp32 store (+ batch offset sC)
// =====================================================================
template <int MODE, bool SPLIT>
__global__ void __launch_bounds__(256, 2)
gemm_tc(const __half* __restrict__ Ah_, const __half* __restrict__ Al_,
        const __half* __restrict__ Bh_, const __half* __restrict__ Bl_,
        void* __restrict__ C0b, void* __restrict__ C1b,
        const float* __restrict__ bias,
        int K, int lda, int ldb, int ldc,
        long sA, long sB, long sC) {
    constexpr int NSTG = SPLIT ? 3 : 6;
    constexpr int NAR  = SPLIT ? 4 : 2;
    constexpr int STGB = NAR * OPB;            // bytes per stage (32768 / 16384)

    extern __shared__ __align__(128) char smem[];

    const __half* Ah = Ah_ + (size_t)blockIdx.z * sA;
    const __half* Al = SPLIT ? (Al_ + (size_t)blockIdx.z * sA) : nullptr;
    const __half* Bh = Bh_ + (size_t)blockIdx.z * sB;
    const __half* Bl = SPLIT ? (Bl_ + (size_t)blockIdx.z * sB) : nullptr;

    const int tid  = threadIdx.x;
    const int lane = tid & 31;
    const int warp = tid >> 5;
    const int wm = warp & 1;     // 2 warp-rows of 64
    const int wn = warp >> 1;    // 4 warp-cols of 32
    const int gm = blockIdx.y * 128;
    const int gn = blockIdx.x * 128;
    const int nk = K >> 5;

    float c[4][4][4];
#pragma unroll
    for (int i = 0; i < 4; i++)
#pragma unroll
        for (int j = 0; j < 4; j++)
#pragma unroll
            for (int r = 0; r < 4; r++) c[i][j][r] = 0.f;

    // per-thread store slot: row = tid>>2 (covers 64 rows per op-half pass), chunk = tid&3
    auto load_stage = [&](int s, int kt) {
        if (kt < nk) {
            char* stg = smem + s * STGB;
            const int k0 = kt * 32;
#pragma unroll
            for (int op = 0; op < NAR; op++) {
                const __half* base;
                int r0, ld;
                if (SPLIT) {
                    base = (op == 0) ? Ah : (op == 1) ? Al : (op == 2) ? Bh : Bl;
                    r0 = (op < 2) ? gm : gn;
                    ld = (op < 2) ? lda : ldb;
                } else {
                    base = (op == 0) ? Ah : Bh;
                    r0 = (op == 0) ? gm : gn;
                    ld = (op == 0) ? lda : ldb;
                }
                char* dst0 = stg + op * OPB;
#pragma unroll
                for (int it = 0; it < 2; it++) {
                    int qq = tid + it * 256;
                    int r = qq >> 2, cc = qq & 3;
                    uint32_t dst = smem_u32(dst0 + swz_off(r, cc));
                    const __half* src = base + (size_t)(r0 + r) * ld + k0 + cc * 8;
                    asm volatile("cp.async.cg.shared.global [%0], [%1], 16;\n"
                                 ::"r"(dst), "l"(src));
                }
            }
        }
        asm volatile("cp.async.commit_group;\n");
    };

    // prologue
#pragma unroll
    for (int t = 0; t < NSTG - 1; t++) load_stage(t, t);

    uint32_t ah[4][4], al[4][4], bh[4][2], bl[4][2];

    auto load_frags = [&](const char* stg, int ks) {
        const char* sa = stg;
        const char* sb = stg + (SPLIT ? 2 : 1) * OPB;
#pragma unroll
        for (int i = 0; i < 4; i++) {
            int row = wm * 64 + i * 16 + (lane & 15);
            uint32_t o = swz_off(row, ks * 2 + (lane >> 4));
            uint32_t a0 = smem_u32(sa + o);
            asm volatile("ldmatrix.sync.aligned.m8n8.x4.shared.b16 {%0,%1,%2,%3}, [%4];"
                         : "=r"(ah[i][0]), "=r"(ah[i][1]), "=r"(ah[i][2]), "=r"(ah[i][3])
                         : "r"(a0));
            if (SPLIT) {
                uint32_t a1 = smem_u32(sa + OPB + o);
                asm volatile("ldmatrix.sync.aligned.m8n8.x4.shared.b16 {%0,%1,%2,%3}, [%4];"
                             : "=r"(al[i][0]), "=r"(al[i][1]), "=r"(al[i][2]), "=r"(al[i][3])
                             : "r"(a1));
            }
        }
#pragma unroll
        for (int j = 0; j < 4; j++) {
            int row = wn * 32 + j * 8 + (lane & 7);
            uint32_t o = swz_off(row, ks * 2 + ((lane >> 3) & 1));
            uint32_t b0 = smem_u32(sb + o);
            asm volatile("ldmatrix.sync.aligned.m8n8.x2.shared.b16 {%0,%1}, [%2];"
                         : "=r"(bh[j][0]), "=r"(bh[j][1]) : "r"(b0));
            if (SPLIT) {
                uint32_t b1 = smem_u32(sb + OPB + o);
                asm volatile("ldmatrix.sync.aligned.m8n8.x2.shared.b16 {%0,%1}, [%2];"
                             : "=r"(bl[j][0]), "=r"(bl[j][1]) : "r"(b1));
            }
        }
    };

#define MMA16(AA, BB_)                                                                       \
    asm volatile("mma.sync.aligned.m16n8k16.row.col.f32.f16.f16.f32 "                        \
                 "{%0,%1,%2,%3}, {%4,%5,%6,%7}, {%8,%9}, {%0,%1,%2,%3};"                     \
                 : "+f"(c[i][j][0]), "+f"(c[i][j][1]), "+f"(c[i][j][2]), "+f"(c[i][j][3])    \
                 : "r"(AA[i][0]), "r"(AA[i][1]), "r"(AA[i][2]), "r"(AA[i][3]),               \
                   "r"(BB_[j][0]), "r"(BB_[j][1]))

    auto domma = [&]() {
#pragma unroll
        for (int i = 0; i < 4; i++)
#pragma unroll
            for (int j = 0; j < 4; j++) MMA16(ah, bh);
        if (SPLIT) {
#pragma unroll
            for (int i = 0; i < 4; i++)
#pragma unroll
                for (int j = 0; j < 4; j++) MMA16(ah, bl);
#pragma unroll
            for (int i = 0; i < 4; i++)
#pragma unroll
                for (int j = 0; j < 4; j++) MMA16(al, bh);
        }
    };
#undef MMA16

    for (int kt = 0; kt < nk; kt++) {
        cpwait<NSTG - 2>();          // stage kt landed
        __syncthreads();             // everyone finished reading slot (kt+NSTG-1)%NSTG last iter

        const char* stg = smem + (kt % NSTG) * STGB;
        load_frags(stg, 0);
        load_stage((kt + NSTG - 1) % NSTG, kt + NSTG - 1);  // overlap LDGSTS issue with MMA
        domma();
        load_frags(stg, 1);
        domma();
    }

    __syncthreads();

    if (MODE == 0) {
        __half* Chi = (__half*)C0b;
        __half* Clo = (__half*)C1b;
#pragma unroll
        for (int i = 0; i < 4; i++)
#pragma unroll
            for (int j = 0; j < 4; j++) {
                int row = gm + wm * 64 + i * 16 + (lane >> 2);
                int col = gn + wn * 32 + j * 8 + ((lane & 3) << 1);
                float b0 = bias[col], b1 = bias[col + 1];
#pragma unroll
                for (int h = 0; h < 2; h++) {
                    float v0 = c[i][j][2 * h + 0] + b0;
                    float v1 = c[i][j][2 * h + 1] + b1;
                    __half h0 = __float2half_rn(v0), h1 = __float2half_rn(v1);
                    __half l0 = __float2half_rn(v0 - __half2float(h0));
                    __half l1 = __float2half_rn(v1 - __half2float(h1));
                    size_t o = (size_t)(row + 8 * h) * ldc + col;
                    *(__half2*)(Chi + o) = __halves2half2(h0, h1);
                    *(__half2*)(Clo + o) = __halves2half2(l0, l1);
                }
            }
    } else if (MODE == 2) {
        float* C = (float*)C0b + (size_t)blockIdx.z * sC;
#pragma unroll
        for (int i = 0; i < 4; i++)
#pragma unroll
            for (int j = 0; j < 4; j++) {
                int row = gm + wm * 64 + i * 16 + (lane >> 2);
                int col = gn + wn * 32 + j * 8 + ((lane & 3) << 1);
                float2 v0; v0.x = c[i][j][0]; v0.y = c[i][j][1];
                float2 v1; v1.x = c[i][j][2]; v1.y = c[i][j][3];
                *(float2*)(C + (size_t)row * ldc + col) = v0;
                *(float2*)(C + (size_t)(row + 8) * ldc + col) = v1;
            }
    } else {  // MODE 1: tanh + transposed fp16 store via smem staging
        __half* st = (__half*)smem;  // 128*136 halves = 34816 B <= stage mem
#pragma unroll
        for (int i = 0; i < 4; i++)
#pragma unroll
            for (int j = 0; j < 4; j++) {
                int row = wm * 64 + i * 16 + (lane >> 2);
                int col = wn * 32 + j * 8 + ((lane & 3) << 1);
                float b0 = bias[gn + col], b1 = bias[gn + col + 1];
                st[(col + 0) * 136 + row + 0] = __float2half_rn(tanhf(c[i][j][0] + b0));
                st[(col + 1) * 136 + row + 0] = __float2half_rn(tanhf(c[i][j][1] + b1));
                st[(col + 0) * 136 + row + 8] = __float2half_rn(tanhf(c[i][j][2] + b0));
                st[(col + 1) * 136 + row + 8] = __float2half_rn(tanhf(c[i][j][3] + b1));
            }
        __syncthreads();
        __half* C = (__half*)C0b;
        for (int qq = tid; qq < 128 * 128 / 8; qq += 256) {
            int n = qq >> 4, m = (qq & 15) << 3;     // 8 halves per thread
            *(uint4*)(C + (size_t)(gn + n) * ldc + gm + m) = *(const uint4*)(st + n * 136 + m);
        }
    }
}

// ---------------- softmax over rows of S (+ int32 bool-mask add) -> fp16 P ----------------
__global__ void softmax_k(const float* __restrict__ S, const int* __restrict__ mask,
                          __half* __restrict__ P) {
    int row = blockIdx.x;
    int b = row >> 11;
    const float* s = S + (size_t)row * SKL;
    const int* mk = mask + (size_t)b * SKL;
    int t = threadIdx.x;

    float vals[8];
    float mx = -3.4e38f;
#pragma unroll
    for (int i = 0; i < 8; i++) {
        int j = t + i * 256;
        float v = s[j] + (mk[j] ? 1.0f : 0.0f);
        vals[i] = v;
        mx = fmaxf(mx, v);
    }
    __shared__ float red[8];
#pragma unroll
    for (int o = 16; o > 0; o >>= 1) mx = fmaxf(mx, __shfl_xor_sync(0xffffffffu, mx, o));
    if ((t & 31) == 0) red[t >> 5] = mx;
    __syncthreads();
    if (t == 0) {
        float v = red[0];
        for (int i = 1; i < 8; i++) v = fmaxf(v, red[i]);
        red[0] = v;
    }
    __syncthreads();
    mx = red[0];

    float sum = 0.f;
#pragma unroll
    for (int i = 0; i < 8; i++) {
        vals[i] = __expf(vals[i] - mx);
        sum += vals[i];
    }
#pragma unroll
    for (int o = 16; o > 0; o >>= 1) sum += __shfl_xor_sync(0xffffffffu, sum, o);
    __syncthreads();
    if ((t & 31) == 0) red[t >> 5] = sum;
    __syncthreads();
    if (t == 0) {
        float v = 0.f;
        for (int i = 0; i < 8; i++) v += red[i];
        red[0] = v;
    }
    __syncthreads();
    float inv = 1.0f / red[0];
#pragma unroll
    for (int i = 0; i < 8; i++) {
        int j = t + i * 256;
        P[(size_t)row * SKL + j] = __float2half_rn(vals[i] * inv);
    }
}

// ---------------- launch ----------------
extern "C" void kernel_launch(void* const* d_in, const int* in_sizes, int n_in,
                              void* d_out, int out_size) {
    const float* q  = (const float*)d_in[0];
    const float* k  = (const float*)d_in[1];
    const float* v  = (const float*)d_in[2];
    const int*   mask = (const int*)d_in[3];
    const float* Wq = (const float*)d_in[4];
    const float* bq = (const float*)d_in[5];
    const float* Wk = (const float*)d_in[6];
    const float* bk = (const float*)d_in[7];
    const float* Wv = (const float*)d_in[8];
    const float* bv = (const float*)d_in[9];

    __half *qh, *ql, *kh, *kl, *vh, *vl;
    __half *Wqh, *Wql, *Wkh, *Wkl, *Wvh, *Wvl;
    __half *Qph, *Qpl, *Kph, *Kpl, *VpT, *P;
    float* S;
    cudaGetSymbolAddress((void**)&qh,  g_qh);  cudaGetSymbolAddress((void**)&ql,  g_ql);
    cudaGetSymbolAddress((void**)&kh,  g_kh);  cudaGetSymbolAddress((void**)&kl,  g_kl);
    cudaGetSymbolAddress((void**)&vh,  g_vh);  cudaGetSymbolAddress((void**)&vl,  g_vl);
    cudaGetSymbolAddress((void**)&Wqh, g_Wqh); cudaGetSymbolAddress((void**)&Wql, g_Wql);
    cudaGetSymbolAddress((void**)&Wkh, g_Wkh); cudaGetSymbolAddress((void**)&Wkl, g_Wkl);
    cudaGetSymbolAddress((void**)&Wvh, g_Wvh); cudaGetSymbolAddress((void**)&Wvl, g_Wvl);
    cudaGetSymbolAddress((void**)&Qph, g_Qph); cudaGetSymbolAddress((void**)&Qpl, g_Qpl);
    cudaGetSymbolAddress((void**)&Kph, g_Kph); cudaGetSymbolAddress((void**)&Kpl, g_Kpl);
    cudaGetSymbolAddress((void**)&VpT, g_VpT);
    cudaGetSymbolAddress((void**)&S,   g_S);
    cudaGetSymbolAddress((void**)&P,   g_P);

    const int SM_SPLIT  = 3 * 4 * OPB;  // 3 stages * 4 ops * 8192 B = 98304
    const int SM_SINGLE = 6 * 2 * OPB;  // 6 stages * 2 ops * 8192 B = 98304
    cudaFuncSetAttribute(gemm_tc<0, true>,  cudaFuncAttributeMaxDynamicSharedMemorySize, SM_SPLIT);
    cudaFuncSetAttribute(gemm_tc<1, true>,  cudaFuncAttributeMaxDynamicSharedMemorySize, SM_SPLIT);
    cudaFuncSetAttribute(gemm_tc<2, true>,  cudaFuncAttributeMaxDynamicSharedMemorySize, SM_SPLIT);
    cudaFuncSetAttribute(gemm_tc<2, false>, cudaFuncAttributeMaxDynamicSharedMemorySize, SM_SINGLE);

    int n4 = BB * SQL * DDIM / 4;
    cvt_split<<<n4 / 256, 256>>>(q, qh, ql, n4);
    cvt_split<<<n4 / 256, 256>>>(k, kh, kl, n4);
    cvt_split<<<n4 / 256, 256>>>(v, vh, vl, n4);

    dim3 wtg(32, 32), wtb(32, 8);
    wtrans_split<<<wtg, wtb>>>(Wq, Wqh, Wql);
    wtrans_split<<<wtg, wtb>>>(Wk, Wkh, Wkl);
    wtrans_split<<<wtg, wtb>>>(Wv, Wvh, Wvl);

    // Projections: M = 16384, N = 1024, K = 1024 (3-pass split)
    gemm_tc<0, true><<<dim3(8, 128, 1), 256, SM_SPLIT>>>(
        qh, ql, Wqh, Wql, Qph, Qpl, bq, 1024, 1024, 1024, 1024, 0, 0, 0);
    gemm_tc<0, true><<<dim3(8, 128, 1), 256, SM_SPLIT>>>(
        kh, kl, Wkh, Wkl, Kph, Kpl, bk, 1024, 1024, 1024, 1024, 0, 0, 0);
    // V projection: tanh + transposed store into VpT[dv][b*SK+sk]
    gemm_tc<1, true><<<dim3(8, 128, 1), 256, SM_SPLIT>>>(
        vh, vl, Wvh, Wvl, VpT, nullptr, bv, 1024, 1024, 1024, BB * SKL, 0, 0, 0);

    // Scores: per batch, S = Qp Kp^T  (M=N=2048, K=1024), 3-pass split
    gemm_tc<2, true><<<dim3(16, 16, BB), 256, SM_SPLIT>>>(
        Qph, Qpl, Kph, Kpl, S, nullptr, nullptr, 1024, 1024, 1024, 2048,
        (long)SQL * DDIM, (long)SKL * DDIM, (long)SQL * SKL);

    // Softmax (+int mask) -> P fp16
    softmax_k<<<BB * SQL, 256>>>(S, mask, P);

    // Output: per batch, O = P · VpT^T  (M=2048, N=1024, K=2048), single-pass fp16
    gemm_tc<2, false><<<dim3(8, 16, BB), 256, SM_SINGLE>>>(
        P, nullptr, VpT, nullptr, d_out, nullptr, nullptr, 2048, 2048, BB * SKL, 1024,
        (long)SQL * SKL, (long)SKL, (long)SQL * DDIM);
}

// round 8
// speedup vs baseline: 1.7867x; 1.0086x over previous
#include <cuda_runtime.h>
#include <cuda_fp16.h>
#include <cstdint>

#define BB 8
#define SQL 2048
#define SKL 2048
#define DDIM 1024

// ---------------- static device scratch (no allocation allowed) ----------------
__device__ __align__(256) __half g_qh [BB * SQL * DDIM];
__device__ __align__(256) __half g_ql [BB * SQL * DDIM];
__device__ __align__(256) __half g_kh [BB * SKL * DDIM];
__device__ __align__(256) __half g_kl [BB * SKL * DDIM];
__device__ __align__(256) __half g_vh [BB * SKL * DDIM];
__device__ __align__(256) __half g_vl [BB * SKL * DDIM];
__device__ __align__(256) __half g_Wqh[DDIM * DDIM];
__device__ __align__(256) __half g_Wql[DDIM * DDIM];
__device__ __align__(256) __half g_Wkh[DDIM * DDIM];
__device__ __align__(256) __half g_Wkl[DDIM * DDIM];
__device__ __align__(256) __half g_Wvh[DDIM * DDIM];
__device__ __align__(256) __half g_Wvl[DDIM * DDIM];
__device__ __align__(256) __half g_Qph[BB * SQL * DDIM];
__device__ __align__(256) __half g_Qpl[BB * SQL * DDIM];
__device__ __align__(256) __half g_Kph[BB * SKL * DDIM];
__device__ __align__(256) __half g_Kpl[BB * SKL * DDIM];
__device__ __align__(256) __half g_VpT[DDIM * BB * SKL];   // [dv][b*SK + sk]
__device__ __align__(256) float  g_S  [(size_t)BB * SQL * SKL];
__device__ __align__(256) __half g_P  [(size_t)BB * SQL * SKL];

__device__ __forceinline__ uint32_t smem_u32(const void* p) {
    return (uint32_t)__cvta_generic_to_shared(p);
}

// ---------------- merged fp32 -> (hi,lo) fp16 split convert (z picks tensor) ----
__global__ void cvt_split3(const float* __restrict__ x0, __half* h0, __half* l0,
                           const float* __restrict__ x1, __half* h1, __half* l1,
                           const float* __restrict__ x2, __half* h2, __half* l2) {
    const float* x = (blockIdx.y == 0) ? x0 : (blockIdx.y == 1) ? x1 : x2;
    __half* hi = (blockIdx.y == 0) ? h0 : (blockIdx.y == 1) ? h1 : h2;
    __half* lo = (blockIdx.y == 0) ? l0 : (blockIdx.y == 1) ? l1 : l2;
    int i = blockIdx.x * blockDim.x + threadIdx.x;
    float4 v = ((const float4*)x)[i];
    __half a0 = __float2half_rn(v.x), a1 = __float2half_rn(v.y);
    __half a2 = __float2half_rn(v.z), a3 = __float2half_rn(v.w);
    __half b0 = __float2half_rn(v.x - __half2float(a0));
    __half b1 = __float2half_rn(v.y - __half2float(a1));
    __half b2 = __float2half_rn(v.z - __half2float(a2));
    __half b3 = __float2half_rn(v.w - __half2float(a3));
    ((__half2*)hi)[2 * i + 0] = __halves2half2(a0, a1);
    ((__half2*)hi)[2 * i + 1] = __halves2half2(a2, a3);
    ((__half2*)lo)[2 * i + 0] = __halves2half2(b0, b1);
    ((__half2*)lo)[2 * i + 1] = __halves2half2(b2, b3);
}

// ---------------- merged weight transpose + split (z picks matrix) ----------------
__global__ void wtrans3(const float* __restrict__ W0, __half* T0h, __half* T0l,
                        const float* __restrict__ W1, __half* T1h, __half* T1l,
                        const float* __restrict__ W2, __half* T2h, __half* T2l) {
    const float* W = (blockIdx.z == 0) ? W0 : (blockIdx.z == 1) ? W1 : W2;
    __half* WTh = (blockIdx.z == 0) ? T0h : (blockIdx.z == 1) ? T1h : T2h;
    __half* WTl = (blockIdx.z == 0) ? T0l : (blockIdx.z == 1) ? T1l : T2l;
    __shared__ float tile[32][33];
    int kb = blockIdx.x * 32, nb = blockIdx.y * 32;
    int tx = threadIdx.x, ty = threadIdx.y;
#pragma unroll
    for (int r = 0; r < 4; r++)
        tile[ty + 8 * r][tx] = W[(size_t)(kb + ty + 8 * r) * DDIM + nb + tx];
    __syncthreads();
#pragma unroll
    for (int r = 0; r < 4; r++) {
        float x = tile[tx][ty + 8 * r];
        __half h = __float2half_rn(x);
        size_t o = (size_t)(nb + ty + 8 * r) * DDIM + kb + tx;
        WTh[o] = h;
        WTl[o] = __float2half_rn(x - __half2float(h));
    }
}

// XOR swizzle: 64-byte k-rows (32 halves), 4 chunks of 16B per row.
#define OPB 8192   // bytes per operand tile: 128 rows * 64 B

__device__ __forceinline__ uint32_t swz_off(int row, int chunk) {
    return (uint32_t)(row * 64 + ((chunk ^ ((row >> 1) & 3)) << 4));
}

template <int N> __device__ __forceinline__ void cpwait() {
    asm volatile("cp.async.wait_group %0;\n" ::"n"(N));
}

// =====================================================================
// Shared GEMM core. MODE_CT: 2 = fp32 store; 3 = runtime mode (0: bias +
// hi/lo split store; 1: tanh+bias, transposed fp16 store).
// SPLIT: 3 mma passes (Ah*Bh + Ah*Bl + Al*Bh), fp32 accum.
// =====================================================================
template <int MODE_CT, bool SPLIT>
__device__ __forceinline__ void gemm_core(
    const __half* __restrict__ Ah, const __half* __restrict__ Al,
    const __half* __restrict__ Bh, const __half* __restrict__ Bl,
    void* __restrict__ C0b, void* __restrict__ C1b,
    const float* __restrict__ bias,
    int K, int lda, int ldb, int ldc, int rtmode, char* smem) {
    constexpr int NSTG = SPLIT ? 3 : 6;
    constexpr int NAR  = SPLIT ? 4 : 2;
    constexpr int STGB = NAR * OPB;

    const int tid  = threadIdx.x;
    const int lane = tid & 31;
    const int warp = tid >> 5;
    const int wm = warp & 1;
    const int wn = warp >> 1;
    const int gm = blockIdx.y * 128;
    const int gn = blockIdx.x * 128;
    const int nk = K >> 5;

    float c[4][4][4];
#pragma unroll
    for (int i = 0; i < 4; i++)
#pragma unroll
        for (int j = 0; j < 4; j++)
#pragma unroll
            for (int r = 0; r < 4; r++) c[i][j][r] = 0.f;

    auto load_stage = [&](int s, int kt) {
        if (kt < nk) {
            char* stg = smem + s * STGB;
            const int k0 = kt * 32;
#pragma unroll
            for (int op = 0; op < NAR; op++) {
                const __half* base;
                int r0, ld;
                if (SPLIT) {
                    base = (op == 0) ? Ah : (op == 1) ? Al : (op == 2) ? Bh : Bl;
                    r0 = (op < 2) ? gm : gn;
                    ld = (op < 2) ? lda : ldb;
                } else {
                    base = (op == 0) ? Ah : Bh;
                    r0 = (op == 0) ? gm : gn;
                    ld = (op == 0) ? lda : ldb;
                }
                char* dst0 = stg + op * OPB;
#pragma unroll
                for (int it = 0; it < 2; it++) {
                    int qq = tid + it * 256;
                    int r = qq >> 2, cc = qq & 3;
                    uint32_t dst = smem_u32(dst0 + swz_off(r, cc));
                    const __half* src = base + (size_t)(r0 + r) * ld + k0 + cc * 8;
                    asm volatile("cp.async.cg.shared.global [%0], [%1], 16;\n"
                                 ::"r"(dst), "l"(src));
                }
            }
        }
        asm volatile("cp.async.commit_group;\n");
    };

#pragma unroll
    for (int t = 0; t < NSTG - 1; t++) load_stage(t, t);

    uint32_t ah[4][4], al[4][4], bh[4][2], bl[4][2];

    auto load_frags = [&](const char* stg, int ks) {
        const char* sa = stg;
        const char* sb = stg + (SPLIT ? 2 : 1) * OPB;
#pragma unroll
        for (int i = 0; i < 4; i++) {
            int row = wm * 64 + i * 16 + (lane & 15);
            uint32_t o = swz_off(row, ks * 2 + (lane >> 4));
            uint32_t a0 = smem_u32(sa + o);
            asm volatile("ldmatrix.sync.aligned.m8n8.x4.shared.b16 {%0,%1,%2,%3}, [%4];"
                         : "=r"(ah[i][0]), "=r"(ah[i][1]), "=r"(ah[i][2]), "=r"(ah[i][3])
                         : "r"(a0));
            if (SPLIT) {
                uint32_t a1 = smem_u32(sa + OPB + o);
                asm volatile("ldmatrix.sync.aligned.m8n8.x4.shared.b16 {%0,%1,%2,%3}, [%4];"
                             : "=r"(al[i][0]), "=r"(al[i][1]), "=r"(al[i][2]), "=r"(al[i][3])
                             : "r"(a1));
            }
        }
        // B via x4: lanes 0-7 -> (j,k0), 8-15 -> (j,k1), 16-23 -> (j+1,k0), 24-31 -> (j+1,k1)
#pragma unroll
        for (int j = 0; j < 4; j += 2) {
            int row = wn * 32 + (j + (lane >> 4)) * 8 + (lane & 7);
            uint32_t o = swz_off(row, ks * 2 + ((lane >> 3) & 1));
            uint32_t b0 = smem_u32(sb + o);
            asm volatile("ldmatrix.sync.aligned.m8n8.x4.shared.b16 {%0,%1,%2,%3}, [%4];"
                         : "=r"(bh[j][0]), "=r"(bh[j][1]), "=r"(bh[j + 1][0]), "=r"(bh[j + 1][1])
                         : "r"(b0));
            if (SPLIT) {
                uint32_t b1 = smem_u32(sb + OPB + o);
                asm volatile("ldmatrix.sync.aligned.m8n8.x4.shared.b16 {%0,%1,%2,%3}, [%4];"
                             : "=r"(bl[j][0]), "=r"(bl[j][1]), "=r"(bl[j + 1][0]), "=r"(bl[j + 1][1])
                             : "r"(b1));
            }
        }
    };

#define MMA16(AA, BB_)                                                                       \
    asm volatile("mma.sync.aligned.m16n8k16.row.col.f32.f16.f16.f32 "                        \
                 "{%0,%1,%2,%3}, {%4,%5,%6,%7}, {%8,%9}, {%0,%1,%2,%3};"                     \
                 : "+f"(c[i][j][0]), "+f"(c[i][j][1]), "+f"(c[i][j][2]), "+f"(c[i][j][3])    \
                 : "r"(AA[i][0]), "r"(AA[i][1]), "r"(AA[i][2]), "r"(AA[i][3]),               \
                   "r"(BB_[j][0]), "r"(BB_[j][1]))

    auto domma = [&]() {
#pragma unroll
        for (int i = 0; i < 4; i++)
#pragma unroll
            for (int j = 0; j < 4; j++) MMA16(ah, bh);
        if (SPLIT) {
#pragma unroll
            for (int i = 0; i < 4; i++)
#pragma unroll
                for (int j = 0; j < 4; j++) MMA16(ah, bl);
#pragma unroll
            for (int i = 0; i < 4; i++)
#pragma unroll
                for (int j = 0; j < 4; j++) MMA16(al, bh);
        }
    };
#undef MMA16

    for (int kt = 0; kt < nk; kt++) {
        cpwait<NSTG - 2>();
        __syncthreads();
        const char* stg = smem + (kt % NSTG) * STGB;
        load_frags(stg, 0);
        load_stage((kt + NSTG - 1) % NSTG, kt + NSTG - 1);
        domma();
        load_frags(stg, 1);
        domma();
    }

    __syncthreads();

    if (MODE_CT == 2) {
        float* C = (float*)C0b;
#pragma unroll
        for (int i = 0; i < 4; i++)
#pragma unroll
            for (int j = 0; j < 4; j++) {
                int row = gm + wm * 64 + i * 16 + (lane >> 2);
                int col = gn + wn * 32 + j * 8 + ((lane & 3) << 1);
                float2 v0; v0.x = c[i][j][0]; v0.y = c[i][j][1];
                float2 v1; v1.x = c[i][j][2]; v1.y = c[i][j][3];
                *(float2*)(C + (size_t)row * ldc + col) = v0;
                *(float2*)(C + (size_t)(row + 8) * ldc + col) = v1;
            }
    } else {
        if (rtmode == 0) {
            __half* Chi = (__half*)C0b;
            __half* Clo = (__half*)C1b;
#pragma unroll
            for (int i = 0; i < 4; i++)
#pragma unroll
                for (int j = 0; j < 4; j++) {
                    int row = gm + wm * 64 + i * 16 + (lane >> 2);
                    int col = gn + wn * 32 + j * 8 + ((lane & 3) << 1);
                    float b0 = bias[col], b1 = bias[col + 1];
#pragma unroll
                    for (int h = 0; h < 2; h++) {
                        float v0 = c[i][j][2 * h + 0] + b0;
                        float v1 = c[i][j][2 * h + 1] + b1;
                        __half h0 = __float2half_rn(v0), h1 = __float2half_rn(v1);
                        __half l0 = __float2half_rn(v0 - __half2float(h0));
                        __half l1 = __float2half_rn(v1 - __half2float(h1));
                        size_t o = (size_t)(row + 8 * h) * ldc + col;
                        *(__half2*)(Chi + o) = __halves2half2(h0, h1);
                        *(__half2*)(Clo + o) = __halves2half2(l0, l1);
                    }
                }
        } else {  // tanh + transposed fp16 store via smem staging
            __half* st = (__half*)smem;  // 128*136 halves = 34816 B
#pragma unroll
            for (int i = 0; i < 4; i++)
#pragma unroll
                for (int j = 0; j < 4; j++) {
                    int row = wm * 64 + i * 16 + (lane >> 2);
                    int col = wn * 32 + j * 8 + ((lane & 3) << 1);
                    float b0 = bias[gn + col], b1 = bias[gn + col + 1];
                    st[(col + 0) * 136 + row + 0] = __float2half_rn(tanhf(c[i][j][0] + b0));
                    st[(col + 1) * 136 + row + 0] = __float2half_rn(tanhf(c[i][j][1] + b1));
                    st[(col + 0) * 136 + row + 8] = __float2half_rn(tanhf(c[i][j][2] + b0));
                    st[(col + 1) * 136 + row + 8] = __float2half_rn(tanhf(c[i][j][3] + b1));
                }
            __syncthreads();
            __half* C = (__half*)C0b;
            for (int qq = tid; qq < 128 * 128 / 8; qq += 256) {
                int n = qq >> 4, m = (qq & 15) << 3;
                *(uint4*)(C + (size_t)(gn + n) * ldc + gm + m) = *(const uint4*)(st + n * 136 + m);
            }
        }
    }
}

// --------- batched GEMM wrapper (scores / PV), fp32 store ---------
template <bool SPLIT>
__global__ void __launch_bounds__(256, 2)
gemm_b(const __half* __restrict__ Ah_, const __half* __restrict__ Al_,
       const __half* __restrict__ Bh_, const __half* __restrict__ Bl_,
       void* __restrict__ C0b, int K, int lda, int ldb, int ldc,
       long sA, long sB, long sC) {
    extern __shared__ __align__(128) char smem[];
    const __half* Ah = Ah_ + (size_t)blockIdx.z * sA;
    const __half* Al = SPLIT ? (Al_ + (size_t)blockIdx.z * sA) : nullptr;
    const __half* Bh = Bh_ + (size_t)blockIdx.z * sB;
    const __half* Bl = SPLIT ? (Bl_ + (size_t)blockIdx.z * sB) : nullptr;
    float* C = (float*)C0b + (size_t)blockIdx.z * sC;
    gemm_core<2, SPLIT>(Ah, Al, Bh, Bl, C, nullptr, nullptr, K, lda, ldb, ldc, 2, smem);
}

// --------- merged projection kernel: z picks {Q, K, V} ---------
struct ProjSet {
    const __half *Ah, *Al, *Bh, *Bl;
    __half *C0, *C1;
    const float* bias;
    int ldc, mode;
};

__global__ void __launch_bounds__(256, 2)
gemm_proj(ProjSet p0, ProjSet p1, ProjSet p2) {
    extern __shared__ __align__(128) char smem[];
    const ProjSet& p = (blockIdx.z == 0) ? p0 : (blockIdx.z == 1) ? p1 : p2;
    gemm_core<3, true>(p.Ah, p.Al, p.Bh, p.Bl, p.C0, p.C1, p.bias,
                       DDIM, DDIM, DDIM, p.ldc, p.mode, smem);
}

// ---------------- softmax over rows of S (+ int32 bool-mask add) -> fp16 P ----------------
__global__ void softmax_k(const float* __restrict__ S, const int* __restrict__ mask,
                          __half* __restrict__ P) {
    int row = blockIdx.x;
    int b = row >> 11;
    const float* s = S + (size_t)row * SKL;
    const int* mk = mask + (size_t)b * SKL;
    int t = threadIdx.x;

    float vals[8];
    float mx = -3.4e38f;
#pragma unroll
    for (int i = 0; i < 8; i++) {
        int j = t + i * 256;
        float v = s[j] + (mk[j] ? 1.0f : 0.0f);
        vals[i] = v;
        mx = fmaxf(mx, v);
    }
    __shared__ float red[8];
#pragma unroll
    for (int o = 16; o > 0; o >>= 1) mx = fmaxf(mx, __shfl_xor_sync(0xffffffffu, mx, o));
    if ((t & 31) == 0) red[t >> 5] = mx;
    __syncthreads();
    if (t == 0) {
        float v = red[0];
        for (int i = 1; i < 8; i++) v = fmaxf(v, red[i]);
        red[0] = v;
    }
    __syncthreads();
    mx = red[0];

    float sum = 0.f;
#pragma unroll
    for (int i = 0; i < 8; i++) {
        vals[i] = __expf(vals[i] - mx);
        sum += vals[i];
    }
#pragma unroll
    for (int o = 16; o > 0; o >>= 1) sum += __shfl_xor_sync(0xffffffffu, sum, o);
    __syncthreads();
    if ((t & 31) == 0) red[t >> 5] = sum;
    __syncthreads();
    if (t == 0) {
        float v = 0.f;
        for (int i = 0; i < 8; i++) v += red[i];
        red[0] = v;
    }
    __syncthreads();
    float inv = 1.0f / red[0];
#pragma unroll
    for (int i = 0; i < 8; i++) {
        int j = t + i * 256;
        P[(size_t)row * SKL + j] = __float2half_rn(vals[i] * inv);
    }
}

// ---------------- launch ----------------
extern "C" void kernel_launch(void* const* d_in, const int* in_sizes, int n_in,
                              void* d_out, int out_size) {
    const float* q  = (const float*)d_in[0];
    const float* k  = (const float*)d_in[1];
    const float* v  = (const float*)d_in[2];
    const int*   mask = (const int*)d_in[3];
    const float* Wq = (const float*)d_in[4];
    const float* bq = (const float*)d_in[5];
    const float* Wk = (const float*)d_in[6];
    const float* bk = (const float*)d_in[7];
    const float* Wv = (const float*)d_in[8];
    const float* bv = (const float*)d_in[9];

    __half *qh, *ql, *kh, *kl, *vh, *vl;
    __half *Wqh, *Wql, *Wkh, *Wkl, *Wvh, *Wvl;
    __half *Qph, *Qpl, *Kph, *Kpl, *VpT, *P;
    float* S;
    cudaGetSymbolAddress((void**)&qh,  g_qh);  cudaGetSymbolAddress((void**)&ql,  g_ql);
    cudaGetSymbolAddress((void**)&kh,  g_kh);  cudaGetSymbolAddress((void**)&kl,  g_kl);
    cudaGetSymbolAddress((void**)&vh,  g_vh);  cudaGetSymbolAddress((void**)&vl,  g_vl);
    cudaGetSymbolAddress((void**)&Wqh, g_Wqh); cudaGetSymbolAddress((void**)&Wql, g_Wql);
    cudaGetSymbolAddress((void**)&Wkh, g_Wkh); cudaGetSymbolAddress((void**)&Wkl, g_Wkl);
    cudaGetSymbolAddress((void**)&Wvh, g_Wvh); cudaGetSymbolAddress((void**)&Wvl, g_Wvl);
    cudaGetSymbolAddress((void**)&Qph, g_Qph); cudaGetSymbolAddress((void**)&Qpl, g_Qpl);
    cudaGetSymbolAddress((void**)&Kph, g_Kph); cudaGetSymbolAddress((void**)&Kpl, g_Kpl);
    cudaGetSymbolAddress((void**)&VpT, g_VpT);
    cudaGetSymbolAddress((void**)&S,   g_S);
    cudaGetSymbolAddress((void**)&P,   g_P);

    const int SM_SPLIT  = 3 * 4 * OPB;  // 98304
    const int SM_SINGLE = 6 * 2 * OPB;  // 98304
    cudaFuncSetAttribute(gemm_proj,     cudaFuncAttributeMaxDynamicSharedMemorySize, SM_SPLIT);
    cudaFuncSetAttribute(gemm_b<true>,  cudaFuncAttributeMaxDynamicSharedMemorySize, SM_SPLIT);
    cudaFuncSetAttribute(gemm_b<false>, cudaFuncAttributeMaxDynamicSharedMemorySize, SM_SINGLE);

    int n4 = BB * SQL * DDIM / 4;
    cvt_split3<<<dim3(n4 / 256, 3), 256>>>(q, qh, ql, k, kh, kl, v, vh, vl);

    wtrans3<<<dim3(32, 32, 3), dim3(32, 8)>>>(Wq, Wqh, Wql, Wk, Wkh, Wkl, Wv, Wvh, Wvl);

    // All 3 projections in one launch: M=16384, N=1024, K=1024 (3-pass split)
    ProjSet pq{qh, ql, Wqh, Wql, Qph, Qpl, bq, 1024, 0};
    ProjSet pk{kh, kl, Wkh, Wkl, Kph, Kpl, bk, 1024, 0};
    ProjSet pv{vh, vl, Wvh, Wvl, VpT, nullptr, bv, BB * SKL, 1};
    gemm_proj<<<dim3(8, 128, 3), 256, SM_SPLIT>>>(pq, pk, pv);

    // Scores: per batch, S = Qp Kp^T (M=N=2048, K=1024), 3-pass split
    gemm_b<true><<<dim3(16, 16, BB), 256, SM_SPLIT>>>(
        Qph, Qpl, Kph, Kpl, S, 1024, 1024, 1024, 2048,
        (long)SQL * DDIM, (long)SKL * DDIM, (long)SQL * SKL);

    // Softmax (+int mask) -> P fp16
    softmax_k<<<BB * SQL, 256>>>(S, mask, P);

    // Output: per batch, O = P · VpT^T (M=2048, N=1024, K=2048), single-pass fp16
    gemm_b<false><<<dim3(8, 16, BB), 256, SM_SINGLE>>>(
        P, nullptr, VpT, nullptr, d_out, 2048, 2048, BB * SKL, 1024,
        (long)SQL * SKL, (long)SKL, (long)SQL * DDIM);
}